// round 3
// baseline (speedup 1.0000x reference)
#include <cuda_runtime.h>

#define Nn 8
#define Cc 64
#define Hh 256
#define Ww 256
#define Pp 16          // cluster: 8 col-groups x 2 ch-groups
#define WC 32
#define FSTR 34        // fb row stride (32 + 2 halo)
#define NT 128
#define HW (Hh*Ww)

// byte offsets inside each CTA's smem (floats laid out from base):
//   Ws    @0      (6144 floats)
//   fb0   @24576  (64*34 floats), fb1 @33280
//   mail0 @41984  (8*64 floats),  mail1 @44032
//   rowbar0 @46080, rowbar1 @46088, mailbar0 @46096, mailbar1 @46104
#define FB_F(b)   (6144 + (b)*2176)
#define FB_B(b)   (24576 + (b)*8704)
#define MAIL_F(b) (10496 + (b)*512)
#define MAIL_B(b) (41984 + (b)*2048)
#define ROWBAR_B(b)  (46080 + (b)*8)
#define MAILBAR_B(b) (46096 + (b)*8)
#define SMEM_BYTES 46208

__device__ float g_stack[(size_t)Nn * Cc * Hh * Ww];

extern __shared__ float sm[];

__device__ __forceinline__ void csync() {
    asm volatile("barrier.cluster.arrive.aligned;" ::: "memory");
    asm volatile("barrier.cluster.wait.aligned;" ::: "memory");
}
__device__ __forceinline__ unsigned mapa_rank(unsigned laddr, unsigned rank) {
    unsigned ra;
    asm("mapa.shared::cluster.u32 %0, %1, %2;" : "=r"(ra) : "r"(laddr), "r"(rank));
    return ra;
}
__device__ __forceinline__ void st_cl_f32(unsigned a, float v) {
    asm volatile("st.shared::cluster.f32 [%0], %1;" :: "r"(a), "f"(v) : "memory");
}
__device__ __forceinline__ void st_cl_b64(unsigned a, unsigned long long v) {
    asm volatile("st.shared::cluster.b64 [%0], %1;" :: "r"(a), "l"(v) : "memory");
}
__device__ __forceinline__ void mbar_init(unsigned a, unsigned cnt) {
    asm volatile("mbarrier.init.shared.b64 [%0], %1;" :: "r"(a), "r"(cnt) : "memory");
}
__device__ __forceinline__ void mbar_arrive_remote(unsigned ra) {
    asm volatile("mbarrier.arrive.release.cluster.shared::cluster.b64 _, [%0];"
                 :: "r"(ra) : "memory");
}
__device__ __forceinline__ void mbar_wait_cl(unsigned a, int phase) {
    asm volatile(
        "{\n\t.reg .pred P;\n"
        "LW_%=:\n\t"
        "mbarrier.try_wait.parity.acquire.cluster.shared::cta.b64 P, [%0], %1, 0x989680;\n\t"
        "@P bra LD_%=;\n\t"
        "bra LW_%=;\n"
        "LD_%=:\n\t}"
        :: "r"(a), "r"(phase) : "memory");
}

// ---- packed f32x2 helpers ----
__device__ __forceinline__ unsigned long long splat2(float a) {
    unsigned long long r; unsigned u = __float_as_uint(a);
    asm("mov.b64 %0, {%1, %1};" : "=l"(r) : "r"(u));
    return r;
}
__device__ __forceinline__ void fma2(unsigned long long& d, unsigned long long a, unsigned long long b) {
    asm("fma.rn.f32x2 %0, %1, %2, %0;" : "+l"(d) : "l"(a), "l"(b));
}
__device__ __forceinline__ unsigned long long add2(unsigned long long a, unsigned long long b) {
    unsigned long long d;
    asm("add.rn.f32x2 %0, %1, %2;" : "=l"(d) : "l"(a), "l"(b));
    return d;
}
__device__ __forceinline__ unsigned long long mul2(unsigned long long a, unsigned long long b) {
    unsigned long long d;
    asm("mul.rn.f32x2 %0, %1, %2;" : "=l"(d) : "l"(a), "l"(b));
    return d;
}
__device__ __forceinline__ void unpack2(unsigned long long v, float& lo, float& hi) {
    unsigned ul, uh;
    asm("mov.b64 {%0, %1}, %2;" : "=r"(ul), "=r"(uh) : "l"(v));
    lo = __uint_as_float(ul); hi = __uint_as_float(uh);
}

__global__ void __launch_bounds__(NT, 1) __cluster_dims__(Pp, 1, 1)
dirconv_kernel(const float* __restrict__ x, const float* __restrict__ Wg,
               float* __restrict__ out)
{
    float* Ws = sm;
    const unsigned smu = (unsigned)__cvta_generic_to_shared(sm);

    const int tid  = threadIdx.x;
    const int lane = tid & 31;
    const int warp = tid >> 5;
    const int ob   = warp * 8;
    unsigned rank;
    asm("mov.u32 %0, %%cluster_ctarank;" : "=r"(rank));
    const int g     = (int)(rank >> 1);
    const int cg    = (int)(rank & 1u);
    const int cbase = cg * 32;
    const int w0    = g * WC;
    const int b     = blockIdx.x / Pp;
    const int hasL  = (g > 0), hasR = (g < 7);

    const float* xb = x + (size_t)b * Cc * HW;
    float* stk      = g_stack + (size_t)b * Cc * HW;
    float* outb     = out + (size_t)b * Cc * HW;

    // peer smem-base addresses (derive everything by byte offset)
    const unsigned pb_partner = mapa_rank(smu, rank ^ 1u);
    const unsigned basr = rank & ~1u;
    const unsigned pbL0 = mapa_rank(smu, hasL ? basr - 2u : 0u);
    const unsigned pbL1 = mapa_rank(smu, hasL ? basr - 1u : 0u);
    const unsigned pbR0 = mapa_rank(smu, hasR ? basr + 2u : 0u);
    const unsigned pbR1 = mapa_rank(smu, hasR ? basr + 3u : 0u);
    unsigned pbM[8];
#pragma unroll
    for (int gg = 0; gg < 8; gg++)
        pbM[gg] = mapa_rank(smu, 2u * (unsigned)gg + (unsigned)cg);

    // init barriers (expected arrivals per phase)
    if (tid == 0) {
        unsigned rowcnt = 1u + 2u * (unsigned)hasL + 2u * (unsigned)hasR;
        mbar_init(smu + ROWBAR_B(0), rowcnt);
        mbar_init(smu + ROWBAR_B(1), rowcnt);
        mbar_init(smu + MAILBAR_B(0), 8u);
        mbar_init(smu + MAILBAR_B(1), 8u);
    }

    // stage weights: Ws[i*96 + tap*32 + ol] = W[cbase+ol][i][1][tap] (bias cancels in IN)
    for (int idx = tid; idx < 6144; idx += NT) {
        int i   = idx / 96;
        int rem = idx - i * 96;
        int tap = rem >> 5;
        int ol  = rem & 31;
        Ws[idx] = Wg[(size_t)(cbase + ol) * 576 + i * 9 + 3 + tap];
    }
    // zero cluster-edge halos in both buffers
    if (g == 0 && tid < 64) { sm[FB_F(0) + tid * FSTR] = 0.f; sm[FB_F(1) + tid * FSTR] = 0.f; }
    if (g == 7 && tid < 64) { sm[FB_F(0) + tid * FSTR + 33] = 0.f; sm[FB_F(1) + tid * FSTR + 33] = 0.f; }

    // t = 0: f[0] = x[0] into fb0 (local), stack, then publish
    float v0[8];
#pragma unroll
    for (int k = 0; k < 8; k++) {
        int chg = cbase + ob + k;
        v0[k] = xb[(size_t)chg * HW + w0 + lane];
        sm[FB_F(0) + chg * FSTR + 1 + lane] = v0[k];
        stk[(size_t)chg * HW + w0 + lane] = v0[k];
    }

    csync();  // all peers resident, barriers initialized, halos zeroed

#pragma unroll
    for (int k = 0; k < 8; k++) {
        int chg = cbase + ob + k;
        unsigned eoff = FB_B(0) + (unsigned)(chg * FSTR + 1 + lane) * 4u;
        st_cl_f32(pb_partner + eoff, v0[k]);
        if (lane == 0 && hasL) {
            unsigned ho = FB_B(0) + (unsigned)(chg * FSTR + 33) * 4u;
            st_cl_f32(pbL0 + ho, v0[k]); st_cl_f32(pbL1 + ho, v0[k]);
        }
        if (lane == 31 && hasR) {
            unsigned ho = FB_B(0) + (unsigned)(chg * FSTR + 0) * 4u;
            st_cl_f32(pbR0 + ho, v0[k]); st_cl_f32(pbR1 + ho, v0[k]);
        }
    }
    __syncthreads();
    if (tid == 0) {
        mbar_arrive_remote(pb_partner + ROWBAR_B(0));
        if (hasL) { mbar_arrive_remote(pbL0 + ROWBAR_B(0)); mbar_arrive_remote(pbL1 + ROWBAR_B(0)); }
        if (hasR) { mbar_arrive_remote(pbR0 + ROWBAR_B(0)); mbar_arrive_remote(pbR1 + ROWBAR_B(0)); }
    }

    int row_ph[2] = {0, 0};
    int mail_ph[2] = {0, 0};

    for (int t = 1; t <= 510; ++t) {
        const int fwd = (t <= 255);
        const int row = fwd ? t : 510 - t;
        const float* __restrict__ src = fwd ? xb : stk;
        float* __restrict__ dst = fwd ? stk : outb;
        const int pr = (t - 1) & 1;   // buffer holding previous row
        const int cb = t & 1;         // buffer for this row's output
        const float* fbr = sm + FB_F(pr);
        float* fbw = sm + FB_F(cb);

        // backward-scan init: out[row 255] = f[255] (own values, self-written -> no sync)
        if (t == 256) {
#pragma unroll
            for (int k = 0; k < 8; k++) {
                int chg = cbase + ob + k;
                outb[(size_t)chg * HW + (size_t)255 * Ww + w0 + lane] =
                    fbr[chg * FSTR + 1 + lane];
            }
        }

        // prefetch residual row (independent of the barrier -> overlaps the wait)
        float xr[8];
        const size_t rb = (size_t)row * Ww + w0 + lane;
#pragma unroll
        for (int k = 0; k < 8; k++)
            xr[k] = src[(size_t)(cbase + ob + k) * HW + rb];

        // wait: previous row fully delivered (partner + halos + own via prior bar.sync)
        mbar_wait_cl(smu + ROWBAR_B(pr), row_ph[pr]);
        row_ph[pr] ^= 1;

        // conv: lane = col, thread owns 8 out channels as 4 f32x2 pairs
        unsigned long long acc[4] = {0ull, 0ull, 0ull, 0ull};
#pragma unroll 8
        for (int i = 0; i < Cc; i++) {
            float a0 = fbr[i * FSTR + lane];
            float a1 = fbr[i * FSTR + lane + 1];
            float a2 = fbr[i * FSTR + lane + 2];
            unsigned long long s0 = splat2(a0), s1 = splat2(a1), s2 = splat2(a2);
            const ulonglong2* wp = (const ulonglong2*)(Ws + i * 96 + ob);
            ulonglong2 wa = wp[0],  wb = wp[1];
            ulonglong2 wc = wp[8],  wd = wp[9];
            ulonglong2 we = wp[16], wf2 = wp[17];
            fma2(acc[0], s0, wa.x); fma2(acc[1], s0, wa.y);
            fma2(acc[2], s0, wb.x); fma2(acc[3], s0, wb.y);
            fma2(acc[0], s1, wc.x); fma2(acc[1], s1, wc.y);
            fma2(acc[2], s1, wd.x); fma2(acc[3], s1, wd.y);
            fma2(acc[0], s2, we.x); fma2(acc[1], s2, we.y);
            fma2(acc[2], s2, wf2.x); fma2(acc[3], s2, wf2.y);
        }

        // butterfly reduce over 32 cols (packed)
        unsigned long long s[4], q[4];
#pragma unroll
        for (int j = 0; j < 4; j++) { s[j] = acc[j]; q[j] = mul2(acc[j], acc[j]); }
#pragma unroll
        for (int off = 16; off >= 1; off >>= 1) {
#pragma unroll
            for (int j = 0; j < 4; j++) {
                s[j] = add2(s[j], __shfl_xor_sync(0xffffffffu, s[j], off));
                q[j] = add2(q[j], __shfl_xor_sync(0xffffffffu, q[j], off));
            }
        }

        // push partial sums to all same-cg col peers' mailboxes (incl. self)
        if (lane < 8) {
            int j = lane & 3;
            int isq = lane >> 2;
            unsigned long long val = isq ? q[j] : s[j];
            unsigned moff = MAIL_B(cb) +
                (unsigned)(g * 64 + isq * 32 + ob + 2 * j) * 4u;
#pragma unroll
            for (int p = 0; p < 8; p++) st_cl_b64(pbM[p] + moff, val);
        }
        __syncthreads();
        if (tid == 0) {
#pragma unroll
            for (int p = 0; p < 8; p++) mbar_arrive_remote(pbM[p] + MAILBAR_B(cb));
        }

        // wait mail, compute per-channel stats locally
        mbar_wait_cl(smu + MAILBAR_B(cb), mail_ph[cb]);
        mail_ph[cb] ^= 1;

        float mean = 0.f, rstd = 0.f;
        if (lane < 8) {
            int ch = ob + lane;
            const float* m = sm + MAIL_F(cb);
            float sv = 0.f, qv = 0.f;
#pragma unroll
            for (int p = 0; p < 8; p++) { sv += m[p * 64 + ch]; qv += m[p * 64 + 32 + ch]; }
            mean = sv * (1.f / 256.f);
            float var = qv * (1.f / 256.f) - mean * mean;
            rstd = rsqrtf(var + 1e-5f);
        }

        // epilogue: normalize + ELU + residual; publish row
        float av[8];
#pragma unroll
        for (int j = 0; j < 4; j++) unpack2(acc[j], av[2 * j], av[2 * j + 1]);
#pragma unroll
        for (int k = 0; k < 8; k++) {
            float m = __shfl_sync(0xffffffffu, mean, k);
            float r = __shfl_sync(0xffffffffu, rstd, k);
            float v = (av[k] - m) * r;
            v = v > 0.f ? v : expm1f(v);
            float fn = v + xr[k];
            int chg = cbase + ob + k;
            fbw[chg * FSTR + 1 + lane] = fn;
            dst[(size_t)chg * HW + rb] = fn;
            unsigned eoff = FB_B(cb) + (unsigned)(chg * FSTR + 1 + lane) * 4u;
            st_cl_f32(pb_partner + eoff, fn);
            if (lane == 0 && hasL) {
                unsigned ho = FB_B(cb) + (unsigned)(chg * FSTR + 33) * 4u;
                st_cl_f32(pbL0 + ho, fn); st_cl_f32(pbL1 + ho, fn);
            }
            if (lane == 31 && hasR) {
                unsigned ho = FB_B(cb) + (unsigned)(chg * FSTR + 0) * 4u;
                st_cl_f32(pbR0 + ho, fn); st_cl_f32(pbR1 + ho, fn);
            }
        }
        __syncthreads();
        if (tid == 0) {
            unsigned rb8 = ROWBAR_B(cb);
            mbar_arrive_remote(pb_partner + rb8);
            if (hasL) { mbar_arrive_remote(pbL0 + rb8); mbar_arrive_remote(pbL1 + rb8); }
            if (hasR) { mbar_arrive_remote(pbR0 + rb8); mbar_arrive_remote(pbR1 + rb8); }
        }
    }

    // no CTA exits while peers' remote stores/arrives may target our smem
    csync();
}

extern "C" void kernel_launch(void* const* d_in, const int* in_sizes, int n_in,
                              void* d_out, int out_size)
{
    (void)in_sizes; (void)n_in; (void)out_size;
    const float* x  = (const float*)d_in[0];
    const float* Wg = (const float*)d_in[1];
    // d_in[2] (bias) cancels through InstanceNorm — skipped.
    float* out = (float*)d_out;

    cudaStreamCaptureStatus cs = cudaStreamCaptureStatusNone;
    cudaStreamIsCapturing(0, &cs);
    if (cs == cudaStreamCaptureStatusNone) {
        cudaFuncSetAttribute(dirconv_kernel,
                             cudaFuncAttributeNonPortableClusterSizeAllowed, 1);
        cudaFuncSetAttribute(dirconv_kernel,
                             cudaFuncAttributeMaxDynamicSharedMemorySize, SMEM_BYTES);
    }

    dirconv_kernel<<<Nn * Pp, NT, SMEM_BYTES>>>(x, Wg, out);
}